// round 15
// baseline (speedup 1.0000x reference)
#include <cuda_runtime.h>
#include <cuda_bf16.h>
#include <cstdint>

// Problem constants
#define B_ 128
#define H_ 512
#define I_ 512
#define SIXH 3072
#define BH (B_ * H_)          // 65536
#define CSZ (B_ * H_ * H_)    // 33554432
#define NSPLIT 6

// ---------------- scratch (no allocs allowed) ----------------
__device__ float g_part[NSPLIT][B_ * SIXH];   // split-K partial gates
__device__ float g_f[BH];
__device__ float g_add[BH];
__device__ float g_o[BH];
__device__ float g_q[BH];
__device__ float g_denom[B_];

// ---------------- packed f32x2 helpers (sm_103a FFMA2 path) ----------------
__device__ __forceinline__ uint64_t pack2(float lo, float hi) {
    uint64_t r;
    asm("mov.b64 %0, {%1, %2};" : "=l"(r) : "f"(lo), "f"(hi));
    return r;
}
__device__ __forceinline__ void ffma2(uint64_t& acc, uint64_t a, uint64_t b) {
    asm("fma.rn.f32x2 %0, %1, %2, %0;" : "+l"(acc) : "l"(a), "l"(b));
}
__device__ __forceinline__ float2 unpack2(uint64_t v) {
    float2 r;
    asm("mov.b64 {%0, %1}, %2;" : "=f"(r.x), "=f"(r.y) : "l"(v));
    return r;
}

// ---------------- Kernel 0: L2 prefetch of C_prev (evict_last) ----------------
// Read-only, no stores, no barriers; runs concurrently with the GEMM.
// 128 MB = 1,048,576 x 128B lines; 1024 blocks x 256 thr x 4 lines.
__global__ __launch_bounds__(256) void prefetch_kernel(const float* __restrict__ C_prev)
{
    const size_t tid = (size_t)blockIdx.x * 256 + threadIdx.x;   // 0..262143
    const char* base = reinterpret_cast<const char*>(C_prev);
    #pragma unroll
    for (int i = 0; i < 4; i++) {
        const char* p = base + (tid + (size_t)i * 262144) * 128;
        asm volatile("prefetch.global.L2::evict_last [%0];" :: "l"(p));
    }
}

// ---------------- Kernel 1: partial gates = x @ W^T (FFMA2, split-K=6) --------
// BM=128 x BN=128 tile, BK=16, 256 threads (8 warps), micro-tile 8x8 via
// 32 packed f32x2 accumulators/thread, double-buffered smem.
// Grid (24, 6) = 144 blocks = one wave. Balanced splits: 2x96 + 4x80.
#define GBM 128
#define GBN 128
#define GBK 16

__global__ __launch_bounds__(256) void gemm_kernel(
    const float* __restrict__ x,      // [128,512]
    const float* __restrict__ W)      // [3072,512]
{
    __shared__ float sA[2][GBK][GBM + 4];   // 16.9 KB
    __shared__ float sB[2][GBK][GBN + 4];   // 16.9 KB

    const int bn = blockIdx.x * GBN;
    const int z  = blockIdx.y;                        // 0..5
    const int k_lo = (z < 2) ? z * 96 : 192 + (z - 2) * 80;
    const int nkt  = (z < 2) ? 6 : 5;

    const int t    = threadIdx.x;
    const int wid  = t >> 5;
    const int lane = t & 31;
    const int wm = wid >> 2;
    const int wn = wid & 3;
    const int mt = lane & 7;
    const int nt = lane >> 3;
    const int arow = wm * 64 + mt * 8;
    const int bcol = wn * 32 + nt * 8;

    const int lr = t >> 1;                // 0..127
    const int lk = (t & 1) * 8;           // 0 or 8

    const float* pA = x + (size_t)lr * I_ + k_lo + lk;
    const float* pB = W + (size_t)(bn + lr) * I_ + k_lo + lk;

    float4 a0, a1, b0, b1;

    a0 = __ldg((const float4*)pA);       a1 = __ldg((const float4*)(pA + 4));
    b0 = __ldg((const float4*)pB);       b1 = __ldg((const float4*)(pB + 4));
    sA[0][lk + 0][lr] = a0.x; sA[0][lk + 1][lr] = a0.y; sA[0][lk + 2][lr] = a0.z; sA[0][lk + 3][lr] = a0.w;
    sA[0][lk + 4][lr] = a1.x; sA[0][lk + 5][lr] = a1.y; sA[0][lk + 6][lr] = a1.z; sA[0][lk + 7][lr] = a1.w;
    sB[0][lk + 0][lr] = b0.x; sB[0][lk + 1][lr] = b0.y; sB[0][lk + 2][lr] = b0.z; sB[0][lk + 3][lr] = b0.w;
    sB[0][lk + 4][lr] = b1.x; sB[0][lk + 5][lr] = b1.y; sB[0][lk + 6][lr] = b1.z; sB[0][lk + 7][lr] = b1.w;
    a0 = __ldg((const float4*)(pA + GBK));  a1 = __ldg((const float4*)(pA + GBK + 4));
    b0 = __ldg((const float4*)(pB + GBK));  b1 = __ldg((const float4*)(pB + GBK + 4));
    __syncthreads();

    uint64_t acc2[8][4];
    #pragma unroll
    for (int i = 0; i < 8; i++)
        #pragma unroll
        for (int j = 0; j < 4; j++) acc2[i][j] = 0ull;

    for (int kt = 0; kt < nkt; kt++) {
        const int cur = kt & 1;
        if (kt < nkt - 1) {
            const int nxt = 1 - cur;
            sA[nxt][lk + 0][lr] = a0.x; sA[nxt][lk + 1][lr] = a0.y; sA[nxt][lk + 2][lr] = a0.z; sA[nxt][lk + 3][lr] = a0.w;
            sA[nxt][lk + 4][lr] = a1.x; sA[nxt][lk + 5][lr] = a1.y; sA[nxt][lk + 6][lr] = a1.z; sA[nxt][lk + 7][lr] = a1.w;
            sB[nxt][lk + 0][lr] = b0.x; sB[nxt][lk + 1][lr] = b0.y; sB[nxt][lk + 2][lr] = b0.z; sB[nxt][lk + 3][lr] = b0.w;
            sB[nxt][lk + 4][lr] = b1.x; sB[nxt][lk + 5][lr] = b1.y; sB[nxt][lk + 6][lr] = b1.z; sB[nxt][lk + 7][lr] = b1.w;
            if (kt < nkt - 2) {
                const int ko = (kt + 2) * GBK;
                a0 = __ldg((const float4*)(pA + ko));  a1 = __ldg((const float4*)(pA + ko + 4));
                b0 = __ldg((const float4*)(pB + ko));  b1 = __ldg((const float4*)(pB + ko + 4));
            }
        }

        #pragma unroll
        for (int k = 0; k < GBK; k++) {
            float4 av0 = *reinterpret_cast<const float4*>(&sA[cur][k][arow]);
            float4 av1 = *reinterpret_cast<const float4*>(&sA[cur][k][arow + 4]);
            float4 bv0 = *reinterpret_cast<const float4*>(&sB[cur][k][bcol]);
            float4 bv1 = *reinterpret_cast<const float4*>(&sB[cur][k][bcol + 4]);
            uint64_t bp[4];
            bp[0] = pack2(bv0.x, bv0.y);
            bp[1] = pack2(bv0.z, bv0.w);
            bp[2] = pack2(bv1.x, bv1.y);
            bp[3] = pack2(bv1.z, bv1.w);
            float a[8] = {av0.x, av0.y, av0.z, av0.w, av1.x, av1.y, av1.z, av1.w};
            #pragma unroll
            for (int i = 0; i < 8; i++) {
                uint64_t ap = pack2(a[i], a[i]);
                #pragma unroll
                for (int j = 0; j < 4; j++)
                    ffma2(acc2[i][j], ap, bp[j]);
            }
        }
        __syncthreads();
    }

    float* out = g_part[z];
    #pragma unroll
    for (int i = 0; i < 8; i++) {
        float2 p0 = unpack2(acc2[i][0]);
        float2 p1 = unpack2(acc2[i][1]);
        float2 p2 = unpack2(acc2[i][2]);
        float2 p3 = unpack2(acc2[i][3]);
        float* row = out + (size_t)(arow + i) * SIXH + bn + bcol;
        *reinterpret_cast<float4*>(row)     = make_float4(p0.x, p0.y, p1.x, p1.y);
        *reinterpret_cast<float4*>(row + 4) = make_float4(p2.x, p2.y, p3.x, p3.y);
    }
}

// ---------------- Kernel 2: gate transforms + n.q reduction ----------------
__global__ __launch_bounds__(512) void gate_kernel(
    const float* __restrict__ m_prev,
    const float* __restrict__ n_prev,
    const float* __restrict__ bias,
    float* __restrict__ out_m,
    float* __restrict__ out_n)
{
    const int b = blockIdx.x;
    const int h = threadIdx.x;
    const int base = b * SIXH;
    const int idx = b * H_ + h;

    float mp = m_prev[idx];
    float np = n_prev[idx];

    float g[6];
    #pragma unroll
    for (int gi = 0; gi < 6; gi++) {
        int off = base + gi * H_ + h;
        float s01 = g_part[0][off] + g_part[1][off];
        float s23 = g_part[2][off] + g_part[3][off];
        float s45 = g_part[4][off] + g_part[5][off];
        g[gi] = ((s01 + s23) + s45) + bias[gi * H_ + h];
    }
    float ig = g[0], fg = g[1], og = g[2], qv = g[3], kk = g[4], vv = g[5];

    float mt = fmaxf(fg + mp, ig);
    float it = expf(ig - mt);
    float ft = expf(fg + mp - mt);
    float kt = 0.04419417382415922f * kk;   // 1/sqrt(512)
    float nt = ft * np + it * kt;

    out_m[idx] = mt;
    out_n[idx] = nt;
    g_f[idx]   = ft;
    g_add[idx] = it * vv * kt;
    g_o[idx]   = 1.0f / (1.0f + expf(-og));
    g_q[idx]   = qv;

    float s = nt * qv;
    #pragma unroll
    for (int off = 16; off; off >>= 1) s += __shfl_xor_sync(0xffffffffu, s, off);

    __shared__ float red[16];
    int w = threadIdx.x >> 5, lane = threadIdx.x & 31;
    if (lane == 0) red[w] = s;
    __syncthreads();
    if (threadIdx.x == 0) {
        float tsum = 0.f;
        #pragma unroll
        for (int i = 0; i < 16; i++) tsum += red[i];
        g_denom[b] = fmaxf(fabsf(tsum), 1e-6f);
    }
}

// ---------------- Kernel 3: C_t update + readout + h_t ----------------
// C_prev reads: __ldcs (hit prefetched L2 lines and demote them).
// out_C writes: __stcs (evict-first, don't displace unread prefetched lines).
__global__ __launch_bounds__(256) void cmain_kernel(
    const float* __restrict__ C_prev,
    float* __restrict__ out_C,
    float* __restrict__ out_h)
{
    __shared__ float sq[H_];
    const int b = blockIdx.x >> 6;            // 64 blocks per batch
    const int row0 = (blockIdx.x & 63) * 8;

    const int w = threadIdx.x >> 5;
    const int lane = threadIdx.x & 31;
    const int i = row0 + w;
    const int bi = b * H_ + i;

    const float4* Cp = reinterpret_cast<const float4*>(C_prev) + (size_t)bi * (H_ / 4);
    float4*       Co = reinterpret_cast<float4*>(out_C)        + (size_t)bi * (H_ / 4);

    float4 c[4];
    #pragma unroll
    for (int t = 0; t < 4; t++) c[t] = __ldcs(Cp + lane + t * 32);

    const float* q = g_q + b * H_;
    for (int h = threadIdx.x; h < H_; h += 256) sq[h] = q[h];
    __syncthreads();

    const float f   = g_f[bi];
    const float add = g_add[bi];
    const float4* q4 = reinterpret_cast<const float4*>(sq);

    float acc = 0.f;
    #pragma unroll
    for (int t = 0; t < 4; t++) {
        int j4 = lane + t * 32;
        float4 r;
        r.x = fmaf(f, c[t].x, add);
        r.y = fmaf(f, c[t].y, add);
        r.z = fmaf(f, c[t].z, add);
        r.w = fmaf(f, c[t].w, add);
        __stcs(Co + j4, r);
        float4 qq = q4[j4];
        acc += r.x * qq.x + r.y * qq.y + r.z * qq.z + r.w * qq.w;
    }

    #pragma unroll
    for (int off = 16; off; off >>= 1) acc += __shfl_xor_sync(0xffffffffu, acc, off);

    if (lane == 0)
        out_h[bi] = g_o[bi] * acc / g_denom[b];
}

// ---------------- streams/events (host-side objects, created at load) ---------
struct HxPipe {
    cudaStream_t sc, sp;
    cudaEvent_t eFork, eJoinC, eJoinP;
    HxPipe() {
        cudaStreamCreateWithFlags(&sc, cudaStreamNonBlocking);
        cudaStreamCreateWithFlags(&sp, cudaStreamNonBlocking);
        cudaEventCreateWithFlags(&eFork, cudaEventDisableTiming);
        cudaEventCreateWithFlags(&eJoinC, cudaEventDisableTiming);
        cudaEventCreateWithFlags(&eJoinP, cudaEventDisableTiming);
    }
};
static HxPipe g_px;

// ---------------- launch: GEMM || C_prev-L2-prefetch, then gate, then cmain ----
extern "C" void kernel_launch(void* const* d_in, const int* in_sizes, int n_in,
                              void* d_out, int out_size)
{
    const float* x      = (const float*)d_in[0];
    // d_in[1] = h_prev (unused by the reference)
    const float* C_prev = (const float*)d_in[2];
    const float* m_prev = (const float*)d_in[3];
    const float* n_prev = (const float*)d_in[4];
    const float* W      = (const float*)d_in[5];
    const float* bias   = (const float*)d_in[6];

    float* out   = (float*)d_out;
    float* out_h = out;                       // [B,H]
    float* out_C = out + BH;                  // [B,H,H]
    float* out_m = out + BH + CSZ;            // [B,H]
    float* out_n = out + BH + CSZ + BH;       // [B,H]

    // fork: compute stream (gemm+gate) and prefetch stream
    cudaEventRecord(g_px.eFork, 0);
    cudaStreamWaitEvent(g_px.sc, g_px.eFork, 0);
    cudaStreamWaitEvent(g_px.sp, g_px.eFork, 0);

    dim3 ggrid(SIXH / GBN, NSPLIT);           // (24, 6) = 144 blocks
    gemm_kernel<<<ggrid, 256, 0, g_px.sc>>>(x, W);
    gate_kernel<<<B_, 512, 0, g_px.sc>>>(m_prev, n_prev, bias, out_m, out_n);

    prefetch_kernel<<<1024, 256, 0, g_px.sp>>>(C_prev);

    // join, then the DRAM-bound pass (reads mostly from L2 now)
    cudaEventRecord(g_px.eJoinC, g_px.sc);
    cudaEventRecord(g_px.eJoinP, g_px.sp);
    cudaStreamWaitEvent((cudaStream_t)0, g_px.eJoinC, 0);
    cudaStreamWaitEvent((cudaStream_t)0, g_px.eJoinP, 0);

    cmain_kernel<<<B_ * 64, 256>>>(C_prev, out_C, out_h);
}

// round 16
// speedup vs baseline: 1.2652x; 1.2652x over previous
#include <cuda_runtime.h>
#include <cuda_bf16.h>
#include <cstdint>

// Problem constants
#define B_ 128
#define H_ 512
#define I_ 512
#define SIXH 3072
#define BH (B_ * H_)          // 65536
#define CSZ (B_ * H_ * H_)    // 33554432
#define NSPLIT 6

// ---------------- scratch (no allocs allowed) ----------------
__device__ float g_part[NSPLIT][B_ * SIXH];   // split-K partial gates
__device__ float g_f[BH];
__device__ float g_add[BH];
__device__ float g_o[BH];
__device__ float g_q[BH];
__device__ float g_denom[B_];

// ---------------- packed f32x2 helpers (sm_103a FFMA2 path) ----------------
__device__ __forceinline__ uint64_t pack2(float lo, float hi) {
    uint64_t r;
    asm("mov.b64 %0, {%1, %2};" : "=l"(r) : "f"(lo), "f"(hi));
    return r;
}
__device__ __forceinline__ void ffma2(uint64_t& acc, uint64_t a, uint64_t b) {
    asm("fma.rn.f32x2 %0, %1, %2, %0;" : "+l"(acc) : "l"(a), "l"(b));
}
__device__ __forceinline__ float2 unpack2(uint64_t v) {
    float2 r;
    asm("mov.b64 {%0, %1}, %2;" : "=f"(r.x), "=f"(r.y) : "l"(v));
    return r;
}

// ---------------- Kernel 1: partial gates = x @ W^T (FFMA2, split-K=6) --------
// BM=128 x BN=128 tile, BK=16, 512 threads (16 warps, 4m x 4n warp grid,
// warp tile 32x32), micro-tile 8x4 per thread (16 FFMA2 / 3 LDS.128 per k),
// double-buffered smem. Grid (24, 6) = 144 blocks = one wave.
// 16 warps/SM = 4 warps/SMSP -> 2x the latency cover of the 256-thr variant.
#define GBM 128
#define GBN 128
#define GBK 16

__global__ __launch_bounds__(512) void gemm_kernel(
    const float* __restrict__ x,      // [128,512]
    const float* __restrict__ W)      // [3072,512]
{
    __shared__ float sA[2][GBK][GBM + 4];   // 16.9 KB
    __shared__ float sB[2][GBK][GBN + 4];   // 16.9 KB

    const int bn = blockIdx.x * GBN;
    const int z  = blockIdx.y;                        // 0..5
    // balanced k split: z<2 -> 96 wide (6 tiles), z>=2 -> 80 wide (5 tiles)
    const int k_lo = (z < 2) ? z * 96 : 192 + (z - 2) * 80;
    const int nkt  = (z < 2) ? 6 : 5;

    const int t    = threadIdx.x;
    const int wid  = t >> 5;
    const int lane = t & 31;
    const int wm = wid >> 2;              // 0..3  (32 rows each)
    const int wn = wid & 3;               // 0..3  (32 cols each)
    const int arow = wm * 32 + (lane & 3) * 8;   // 8 rows
    const int bcol = wn * 32 + (lane >> 2) * 4;  // 4 cols

    // loaders: each tile 128x16 = 512 float4 -> exactly 1 float4 per thread
    const int lr = t >> 2;                // 0..127
    const int lk = (t & 3) * 4;           // 0,4,8,12

    const float* pA = x + (size_t)lr * I_ + k_lo + lk;
    const float* pB = W + (size_t)(bn + lr) * I_ + k_lo + lk;

    float4 ra, rb;

    // prologue: tile0 -> buf0, prefetch tile1 -> regs
    ra = __ldg((const float4*)pA);
    rb = __ldg((const float4*)pB);
    sA[0][lk + 0][lr] = ra.x; sA[0][lk + 1][lr] = ra.y; sA[0][lk + 2][lr] = ra.z; sA[0][lk + 3][lr] = ra.w;
    sB[0][lk + 0][lr] = rb.x; sB[0][lk + 1][lr] = rb.y; sB[0][lk + 2][lr] = rb.z; sB[0][lk + 3][lr] = rb.w;
    ra = __ldg((const float4*)(pA + GBK));
    rb = __ldg((const float4*)(pB + GBK));
    __syncthreads();

    // 8 rows x 2 column-pairs of packed accumulators (8x4 micro-tile)
    uint64_t acc2[8][2];
    #pragma unroll
    for (int i = 0; i < 8; i++) { acc2[i][0] = 0ull; acc2[i][1] = 0ull; }

    for (int kt = 0; kt < nkt; kt++) {
        const int cur = kt & 1;
        if (kt < nkt - 1) {
            const int nxt = 1 - cur;
            sA[nxt][lk + 0][lr] = ra.x; sA[nxt][lk + 1][lr] = ra.y; sA[nxt][lk + 2][lr] = ra.z; sA[nxt][lk + 3][lr] = ra.w;
            sB[nxt][lk + 0][lr] = rb.x; sB[nxt][lk + 1][lr] = rb.y; sB[nxt][lk + 2][lr] = rb.z; sB[nxt][lk + 3][lr] = rb.w;
            if (kt < nkt - 2) {
                const int ko = (kt + 2) * GBK;
                ra = __ldg((const float4*)(pA + ko));
                rb = __ldg((const float4*)(pB + ko));
            }
        }

        #pragma unroll
        for (int k = 0; k < GBK; k++) {
            float4 av0 = *reinterpret_cast<const float4*>(&sA[cur][k][arow]);
            float4 av1 = *reinterpret_cast<const float4*>(&sA[cur][k][arow + 4]);
            float4 bv  = *reinterpret_cast<const float4*>(&sB[cur][k][bcol]);
            uint64_t bp0 = pack2(bv.x, bv.y);
            uint64_t bp1 = pack2(bv.z, bv.w);
            float a[8] = {av0.x, av0.y, av0.z, av0.w, av1.x, av1.y, av1.z, av1.w};
            #pragma unroll
            for (int i = 0; i < 8; i++) {
                uint64_t ap = pack2(a[i], a[i]);
                ffma2(acc2[i][0], ap, bp0);
                ffma2(acc2[i][1], ap, bp1);
            }
        }
        __syncthreads();
    }

    float* out = g_part[z];
    #pragma unroll
    for (int i = 0; i < 8; i++) {
        float2 p0 = unpack2(acc2[i][0]);
        float2 p1 = unpack2(acc2[i][1]);
        *reinterpret_cast<float4*>(out + (size_t)(arow + i) * SIXH + bn + bcol) =
            make_float4(p0.x, p0.y, p1.x, p1.y);
    }
}

// ---------------- Kernel 2: gate transforms + n.q reduction (PDL over gemm) ----
__global__ __launch_bounds__(512) void gate_kernel(
    const float* __restrict__ m_prev,
    const float* __restrict__ n_prev,
    const float* __restrict__ bias,
    float* __restrict__ out_m,
    float* __restrict__ out_n)
{
    const int b = blockIdx.x;
    const int h = threadIdx.x;
    const int base = b * SIXH;
    const int idx = b * H_ + h;

    // prologue loads independent of gemm output
    float mp = m_prev[idx];
    float np = n_prev[idx];
    float bs[6];
    #pragma unroll
    for (int gi = 0; gi < 6; gi++) bs[gi] = bias[gi * H_ + h];

    cudaGridDependencySynchronize();   // wait for gemm partials

    float g[6];
    #pragma unroll
    for (int gi = 0; gi < 6; gi++) {
        int off = base + gi * H_ + h;
        float s01 = g_part[0][off] + g_part[1][off];
        float s23 = g_part[2][off] + g_part[3][off];
        float s45 = g_part[4][off] + g_part[5][off];
        g[gi] = ((s01 + s23) + s45) + bs[gi];
    }
    float ig = g[0], fg = g[1], og = g[2], qv = g[3], kk = g[4], vv = g[5];

    float mt = fmaxf(fg + mp, ig);
    float it = expf(ig - mt);
    float ft = expf(fg + mp - mt);
    float kt = 0.04419417382415922f * kk;   // 1/sqrt(512)
    float nt = ft * np + it * kt;

    out_m[idx] = mt;
    out_n[idx] = nt;
    g_f[idx]   = ft;
    g_add[idx] = it * vv * kt;
    g_o[idx]   = 1.0f / (1.0f + expf(-og));
    g_q[idx]   = qv;

    // deterministic block reduce of nt*qv over 512 threads
    float s = nt * qv;
    #pragma unroll
    for (int off = 16; off; off >>= 1) s += __shfl_xor_sync(0xffffffffu, s, off);

    __shared__ float red[16];
    int w = threadIdx.x >> 5, lane = threadIdx.x & 31;
    if (lane == 0) red[w] = s;
    __syncthreads();
    if (threadIdx.x == 0) {
        float tsum = 0.f;
        #pragma unroll
        for (int i = 0; i < 16; i++) tsum += red[i];
        g_denom[b] = fmaxf(fabsf(tsum), 1e-6f);
    }
}

// ---------------- Kernel 3: C_t update + readout + h_t (PDL over gate) ---------
__global__ __launch_bounds__(256) void cmain_kernel(
    const float* __restrict__ C_prev,
    float* __restrict__ out_C,
    float* __restrict__ out_h)
{
    __shared__ float sq[H_];
    const int b = blockIdx.x >> 6;            // 64 blocks per batch
    const int row0 = (blockIdx.x & 63) * 8;

    const int w = threadIdx.x >> 5;
    const int lane = threadIdx.x & 31;
    const int i = row0 + w;
    const int bi = b * H_ + i;

    const float4* Cp = reinterpret_cast<const float4*>(C_prev) + (size_t)bi * (H_ / 4);
    float4*       Co = reinterpret_cast<float4*>(out_C)        + (size_t)bi * (H_ / 4);

    // issue the big DRAM reads before waiting on the upstream grid
    float4 c[4];
    #pragma unroll
    for (int t = 0; t < 4; t++) c[t] = __ldcs(Cp + lane + t * 32);

    cudaGridDependencySynchronize();   // wait for gate outputs

    const float* q = g_q + b * H_;
    for (int h = threadIdx.x; h < H_; h += 256) sq[h] = q[h];
    __syncthreads();

    const float f   = g_f[bi];
    const float add = g_add[bi];
    const float4* q4 = reinterpret_cast<const float4*>(sq);

    float acc = 0.f;
    #pragma unroll
    for (int t = 0; t < 4; t++) {
        int j4 = lane + t * 32;
        float4 r;
        r.x = fmaf(f, c[t].x, add);
        r.y = fmaf(f, c[t].y, add);
        r.z = fmaf(f, c[t].z, add);
        r.w = fmaf(f, c[t].w, add);
        __stcs(Co + j4, r);
        float4 qq = q4[j4];
        acc += r.x * qq.x + r.y * qq.y + r.z * qq.z + r.w * qq.w;
    }

    #pragma unroll
    for (int off = 16; off; off >>= 1) acc += __shfl_xor_sync(0xffffffffu, acc, off);

    if (lane == 0)
        out_h[bi] = g_o[bi] * acc / g_denom[b];
}

// ---------------- launch: serial stream + PDL overlap --------------------------
extern "C" void kernel_launch(void* const* d_in, const int* in_sizes, int n_in,
                              void* d_out, int out_size)
{
    const float* x      = (const float*)d_in[0];
    // d_in[1] = h_prev (unused by the reference)
    const float* C_prev = (const float*)d_in[2];
    const float* m_prev = (const float*)d_in[3];
    const float* n_prev = (const float*)d_in[4];
    const float* W      = (const float*)d_in[5];
    const float* bias   = (const float*)d_in[6];

    float* out   = (float*)d_out;
    float* out_h = out;                       // [B,H]
    float* out_C = out + BH;                  // [B,H,H]
    float* out_m = out + BH + CSZ;            // [B,H]
    float* out_n = out + BH + CSZ + BH;       // [B,H]

    // 1) GEMM (plain launch)
    dim3 ggrid(SIXH / GBN, NSPLIT);           // (24, 6) = 144 blocks = one wave
    gemm_kernel<<<ggrid, 512>>>(x, W);

    // 2) gate with programmatic stream serialization (overlaps gemm tail)
    {
        cudaLaunchConfig_t cfg = {};
        cfg.gridDim = dim3(B_);
        cfg.blockDim = dim3(512);
        cfg.stream = 0;
        cudaLaunchAttribute attr[1];
        attr[0].id = cudaLaunchAttributeProgrammaticStreamSerialization;
        attr[0].val.programmaticStreamSerializationAllowed = 1;
        cfg.attrs = attr;
        cfg.numAttrs = 1;
        cudaLaunchKernelEx(&cfg, gate_kernel, m_prev, n_prev, bias, out_m, out_n);
    }

    // 3) cmain with programmatic stream serialization (C_prev loads overlap gate)
    {
        cudaLaunchConfig_t cfg = {};
        cfg.gridDim = dim3(B_ * 64);
        cfg.blockDim = dim3(256);
        cfg.stream = 0;
        cudaLaunchAttribute attr[1];
        attr[0].id = cudaLaunchAttributeProgrammaticStreamSerialization;
        attr[0].val.programmaticStreamSerializationAllowed = 1;
        cfg.attrs = attr;
        cfg.numAttrs = 1;
        cudaLaunchKernelEx(&cfg, cmain_kernel, C_prev, out_C, out_h);
    }
}